// round 2
// baseline (speedup 1.0000x reference)
#include <cuda_runtime.h>

// YOLO loss, sm_103a — round 2: decoupled, high-occupancy formulation.
//
// loss = Σ_valid_targets [ 5*coord_sq + cls_sq ]                (gather, 84 ch of box0)
//      + 0.5 * ( Σ_all conf^2  -  Σ_{unique obj cells} conf0^2 )  (coalesced + dedup'd sub)
//   all divided by BATCH.
//
// One warp per target (6400 warps), conf^2 as float4-coalesced reduction,
// per-(b,cell) dedup via global bitmask + atomicOr.

#define S_GRID   26
#define NCH      255
#define CELLS    676            // 26*26
#define BATCH_N  128
#define T_TGT    50
#define L_COORD  5.0f
#define L_NOOBJ  0.5f

#define TGT_BLOCKS   800        // 800 * 8 warps = 6400 targets
#define CONF_BLOCKS  112
#define MASK_WORDS   (BATCH_N * 32)   // 676 bits -> 22 words, padded to 32

__device__ unsigned int g_objmask[MASK_WORDS];

__global__ void yolo_init(float* out)
{
    int i = blockIdx.x * 256 + threadIdx.x;
    if (i < MASK_WORDS) g_objmask[i] = 0u;
    if (i == 0) out[0] = 0.0f;
}

__global__ __launch_bounds__(256)
void yolo_loss_kernel(const float* __restrict__ pred,
                      const float* __restrict__ tgt,
                      float* __restrict__ out)
{
    const int tid  = threadIdx.x;
    const int lane = tid & 31;
    const int warp = tid >> 5;

    __shared__ float s_warp[8];

    float acc = 0.0f;

    if (blockIdx.x < TGT_BLOCKS) {
        // ---------------- target gather: one warp per target ----------------
        const int gtid = blockIdx.x * 8 + warp;          // 0..6399
        const int b    = gtid / T_TGT;
        const float* tb = tgt + (size_t)gtid * 5;

        const float clsf = __ldg(tb + 0);
        const float cx   = __ldg(tb + 1);
        const float cy   = __ldg(tb + 2);

        int gx = (int)(cx * S_GRID);        // trunc == floor for cx >= 0
        int gy = (int)(cy * S_GRID);
        const bool valid = (gx < S_GRID) && (gy < S_GRID);

        float wsum = 0.0f;
        if (valid) {
            gx = min(max(gx, 0), S_GRID - 1);
            gy = min(max(gy, 0), S_GRID - 1);
            const int cell = gy * S_GRID + gx;
            const int clsi = (int)clsf;
            const float* pb = pred + (size_t)b * NCH * CELLS + cell;

            const int c = 1 + lane;
            // three strided channel gathers, issued back-to-back (MLP=3)
            const float p0 = __ldg(pb + (size_t)c * CELLS);          // ch 1..32
            const float p1 = __ldg(pb + (size_t)(c + 32) * CELLS);   // ch 33..64
            const float p2 = (lane < 20) ? __ldg(pb + (size_t)(c + 64) * CELLS)
                                         : 0.0f;                     // ch 65..84

            // ch 1..4: coord (weight 5), ch>=5: class one-hot (weight 1)
            float tv0, w0;
            if (c <= 4) { tv0 = __ldg(tb + c); w0 = L_COORD; }
            else        { tv0 = ((c - 5) == clsi) ? 1.0f : 0.0f; w0 = 1.0f; }
            const float tv1 = ((c + 27) == clsi) ? 1.0f : 0.0f;      // ch 33..64 -> cls 28..59
            const float tv2 = ((c + 59) == clsi) ? 1.0f : 0.0f;      // ch 65..84 -> cls 60..79

            const float d0 = p0 - tv0;
            const float d1 = p1 - tv1;
            const float d2 = p2 - tv2;
            wsum = w0 * d0 * d0 + d1 * d1;
            if (lane < 20) wsum = fmaf(d2, d2, wsum);

            // dedup'd subtraction of obj-cell conf0^2 from the noobj full-sum
            if (lane == 0) {
                const unsigned bit = 1u << (cell & 31);
                const unsigned old = atomicOr(&g_objmask[b * 32 + (cell >> 5)], bit);
                if (!(old & bit)) {
                    const float conf = __ldg(pb);                    // channel 0
                    wsum = fmaf(-L_NOOBJ * conf, conf, wsum);
                }
            }
        }
        #pragma unroll
        for (int off = 16; off; off >>= 1)
            wsum += __shfl_down_sync(0xffffffffu, wsum, off);
        if (lane == 0) acc = wsum;
    } else {
        // ------------- conf^2 full sum: coalesced float4 sweep ---------------
        // items: 128 images * 3 conf channels * 169 float4 = 64896
        const int start  = (blockIdx.x - TGT_BLOCKS) * 256 + tid;
        const int stride = CONF_BLOCKS * 256;
        float csum = 0.0f;
        for (int i = start; i < BATCH_N * 3 * 169; i += stride) {
            const int b  = i / 507;           // 3*169
            const int r  = i - b * 507;
            const int ch = r / 169;           // 0,1,2 -> channels 0,85,170
            const int j  = r - ch * 169;
            const float4 v = __ldg((const float4*)(pred
                              + (size_t)b * NCH * CELLS
                              + (size_t)(ch * 85) * CELLS) + j);
            csum += v.x * v.x + v.y * v.y + v.z * v.z + v.w * v.w;
        }
        acc = L_NOOBJ * csum;
        #pragma unroll
        for (int off = 16; off; off >>= 1)
            acc += __shfl_down_sync(0xffffffffu, acc, off);
        if (lane != 0) acc = 0.0f;
    }

    // ---------------- block reduce + single atomic per block ----------------
    if (lane == 0) s_warp[warp] = acc;
    __syncthreads();
    if (warp == 0) {
        float v = (lane < 8) ? s_warp[lane] : 0.0f;
        #pragma unroll
        for (int off = 4; off; off >>= 1)
            v += __shfl_down_sync(0xffffffffu, v, off);
        if (lane == 0 && v != 0.0f)
            atomicAdd(out, v * (1.0f / BATCH_N));
    }
}

extern "C" void kernel_launch(void* const* d_in, const int* in_sizes, int n_in,
                              void* d_out, int out_size)
{
    const float* pred = (const float*)d_in[0];
    const float* tgt  = (const float*)d_in[1];
    float* out = (float*)d_out;

    yolo_init<<<(MASK_WORDS + 255) / 256, 256>>>(out);
    yolo_loss_kernel<<<TGT_BLOCKS + CONF_BLOCKS, 256>>>(pred, tgt, out);
}

// round 3
// speedup vs baseline: 1.1403x; 1.1403x over previous
#include <cuda_runtime.h>

// YOLO loss, sm_103a — round 3: single launch, stateless dedup.
//
// loss = Σ_valid_targets [ 5*coord_sq + cls_sq ]                 (warp-per-target gather)
//      + 0.5 * ( Σ_all conf^2  -  Σ_{unique obj cells} conf0^2 ) (coalesced + in-warp dedup)
//   all / BATCH.
//
// Dedup: target t subtracts conf0^2 iff no valid earlier target t'<t of the same
// image maps to the same cell — recomputed in-warp, no global mask, no init kernel.
// Output via last-block-done pattern (self-resetting accumulator) => ONE launch.

#define S_GRID   26
#define NCH      255
#define CELLS    676
#define BATCH_N  128
#define T_TGT    50
#define L_COORD  5.0f
#define L_NOOBJ  0.5f

#define TGT_BLOCKS   800                 // 800 * 8 warps = 6400 targets
#define CONF_BLOCKS  112
#define NBLOCKS      (TGT_BLOCKS + CONF_BLOCKS)

__device__ float    g_acc = 0.0f;        // reset by last block each call
__device__ unsigned g_cnt = 0u;

__global__ __launch_bounds__(256)
void yolo_loss_kernel(const float* __restrict__ pred,
                      const float* __restrict__ tgt,
                      float* __restrict__ out)
{
    const int tid  = threadIdx.x;
    const int lane = tid & 31;
    const int warp = tid >> 5;

    __shared__ float s_warp[8];

    float acc = 0.0f;

    if (blockIdx.x < TGT_BLOCKS) {
        // ------------- target gather: one warp per target ----------------
        const int gtid = blockIdx.x * 8 + warp;          // 0..6399
        const int b    = gtid / T_TGT;
        const int t    = gtid - b * T_TGT;
        const float* tgb = tgt + (size_t)b * T_TGT * 5;

        const float clsf = __ldg(tgb + t * 5 + 0);
        const float cx   = __ldg(tgb + t * 5 + 1);
        const float cy   = __ldg(tgb + t * 5 + 2);

        int gx = (int)(cx * S_GRID);       // trunc == floor for cx >= 0
        int gy = (int)(cy * S_GRID);
        const bool valid = (gx < S_GRID) && (gy < S_GRID);

        float wsum = 0.0f;
        if (valid) {
            gx = min(max(gx, 0), S_GRID - 1);
            gy = min(max(gy, 0), S_GRID - 1);
            const int cell = gy * S_GRID + gx;
            const int clsi = (int)clsf;
            const float* pb = pred + (size_t)b * NCH * CELLS + cell;

            const int c = 1 + lane;
            // three strided channel gathers, back-to-back (MLP=3)
            const float p0 = __ldg(pb + (size_t)c * CELLS);          // ch 1..32
            const float p1 = __ldg(pb + (size_t)(c + 32) * CELLS);   // ch 33..64
            const float p2 = (lane < 20) ? __ldg(pb + (size_t)(c + 64) * CELLS)
                                         : 0.0f;                     // ch 65..84

            // ---- stateless dedup: any VALID earlier target on the same cell? ----
            bool dup = false;
            if (lane < t) {                                  // probe target 'lane'
                const float ex = __ldg(tgb + lane * 5 + 1);
                const float ey = __ldg(tgb + lane * 5 + 2);
                const int egx = (int)(ex * S_GRID);
                const int egy = (int)(ey * S_GRID);
                if (egx < S_GRID && egy < S_GRID) {
                    const int ec = min(max(egy,0),S_GRID-1) * S_GRID
                                 + min(max(egx,0),S_GRID-1);
                    dup = (ec == cell);
                }
            }
            const int t2 = lane + 32;
            if (t2 < t) {                                    // probe target 'lane+32'
                const float ex = __ldg(tgb + t2 * 5 + 1);
                const float ey = __ldg(tgb + t2 * 5 + 2);
                const int egx = (int)(ex * S_GRID);
                const int egy = (int)(ey * S_GRID);
                if (egx < S_GRID && egy < S_GRID) {
                    const int ec = min(max(egy,0),S_GRID-1) * S_GRID
                                 + min(max(egx,0),S_GRID-1);
                    dup = dup || (ec == cell);
                }
            }
            const bool first = !__any_sync(0xffffffffu, dup);

            // ch 1..4: coord (weight 5) ; ch>=5: class one-hot (weight 1)
            float tv0, w0;
            if (c <= 4) { tv0 = __ldg(tgb + t * 5 + c); w0 = L_COORD; }
            else        { tv0 = ((c - 5) == clsi) ? 1.0f : 0.0f; w0 = 1.0f; }
            const float tv1 = ((c + 27) == clsi) ? 1.0f : 0.0f;
            const float tv2 = ((c + 59) == clsi) ? 1.0f : 0.0f;

            const float d0 = p0 - tv0;
            const float d1 = p1 - tv1;
            const float d2 = p2 - tv2;
            wsum = w0 * d0 * d0 + d1 * d1;
            if (lane < 20) wsum = fmaf(d2, d2, wsum);

            if (lane == 0 && first) {
                const float conf = __ldg(pb);                // channel 0
                wsum = fmaf(-L_NOOBJ * conf, conf, wsum);    // dedup'd subtraction
            }
        }
        #pragma unroll
        for (int off = 16; off; off >>= 1)
            wsum += __shfl_down_sync(0xffffffffu, wsum, off);
        if (lane == 0) acc = wsum;
    } else {
        // ------------- conf^2 full sum: coalesced float4 sweep -------------
        const int start  = (blockIdx.x - TGT_BLOCKS) * 256 + tid;
        const int stride = CONF_BLOCKS * 256;
        float csum = 0.0f;
        for (int i = start; i < BATCH_N * 3 * 169; i += stride) {
            const int b  = i / 507;             // 3*169
            const int r  = i - b * 507;
            const int ch = r / 169;             // channels 0, 85, 170
            const int j  = r - ch * 169;
            const float4 v = __ldg((const float4*)(pred
                              + (size_t)b * NCH * CELLS
                              + (size_t)(ch * 85) * CELLS) + j);
            csum += v.x * v.x + v.y * v.y + v.z * v.z + v.w * v.w;
        }
        acc = L_NOOBJ * csum;
        #pragma unroll
        for (int off = 16; off; off >>= 1)
            acc += __shfl_down_sync(0xffffffffu, acc, off);
        if (lane != 0) acc = 0.0f;
    }

    // --------- block reduce, then last-block-done finalization ---------
    if (lane == 0) s_warp[warp] = acc;
    __syncthreads();
    if (tid == 0) {
        float v = s_warp[0];
        #pragma unroll
        for (int wph = 1; wph < 8; wph++) v += s_warp[wph];
        if (v != 0.0f) atomicAdd(&g_acc, v);
        __threadfence();
        const unsigned ticket = atomicAdd(&g_cnt, 1u);
        if (ticket == NBLOCKS - 1) {
            const float total = atomicAdd(&g_acc, 0.0f);     // coherent read
            out[0] = total * (1.0f / BATCH_N);
            g_acc = 0.0f;                                    // replay-safe reset
            g_cnt = 0u;
        }
    }
}

extern "C" void kernel_launch(void* const* d_in, const int* in_sizes, int n_in,
                              void* d_out, int out_size)
{
    const float* pred = (const float*)d_in[0];
    const float* tgt  = (const float*)d_in[1];
    float* out = (float*)d_out;

    yolo_loss_kernel<<<NBLOCKS, 256>>>(pred, tgt, out);
}

// round 5
// speedup vs baseline: 1.2127x; 1.0635x over previous
#include <cuda_runtime.h>

// YOLO loss, sm_103a — round 4: transposed gather (lanes = targets, loop = channels).
// One warp = (image, target-half, channel-chunk of 12). Warp-LDGs now span one
// 2704B channel row instead of 32 rows -> coalesced sectors, DRAM-row-friendly.

#define S_GRID   26
#define NCH      255
#define CELLS    676
#define BATCH_N  128
#define T_TGT    50
#define L_COORD  5.0f
#define L_NOOBJ  0.5f

#define NCHUNK   7                   // 7 chunks * 12 channels = ch 1..84
#define TGT_WARPS  (BATCH_N * 2 * NCHUNK)   // 1792
#define TGT_BLOCKS (TGT_WARPS / 8)          // 224
#define CONF_BLOCKS 112
#define NBLOCKS    (TGT_BLOCKS + CONF_BLOCKS)

__device__ float    g_acc = 0.0f;    // reset by last block each call
__device__ unsigned g_cnt = 0u;

__global__ __launch_bounds__(256)
void yolo_loss_kernel(const float* __restrict__ pred,
                      const float* __restrict__ tgt,
                      float* __restrict__ out)
{
    const int tid  = threadIdx.x;
    const int lane = tid & 31;
    const int warp = tid >> 5;

    __shared__ float s_warp[8];

    float acc = 0.0f;

    if (blockIdx.x < TGT_BLOCKS) {
        // ---- target gather: warp = (image b, half h, channel chunk q) ----
        const int gw  = blockIdx.x * 8 + warp;      // 0..1791
        const int b   = gw / (2 * NCHUNK);
        const int rem = gw - b * (2 * NCHUNK);
        const int h   = rem / NCHUNK;               // 0 or 1
        const int q   = rem - h * NCHUNK;           // 0..6

        const int  t   = h * 32 + lane;             // this lane's target
        const bool tin = (t < T_TGT);
        const float* tb = tgt + ((size_t)b * T_TGT + t) * 5;

        float clsf = 0.0f, cx = 2.0f, cy = 2.0f;    // cx=2 -> invalid sentinel
        if (tin) {
            clsf = __ldg(tb + 0);
            cx   = __ldg(tb + 1);
            cy   = __ldg(tb + 2);
        }
        const int gx = (int)(cx * S_GRID);          // trunc == floor (cx >= 0)
        const int gy = (int)(cy * S_GRID);
        const bool valid = tin && (gx < S_GRID) && (gy < S_GRID);
        const int cell = min(max(gy, 0), S_GRID - 1) * S_GRID
                       + min(max(gx, 0), S_GRID - 1);
        const int clsi = (int)clsf;

        const float* pb = pred + (size_t)b * NCH * CELLS;
        const int c0 = 1 + q * 12;
        const float* gp = pb + (size_t)c0 * CELLS + cell;

        // 12 independent warp-coalesced gathers within channel rows
        float sum = 0.0f;
        #pragma unroll
        for (int k = 0; k < 12; k++) {
            const int c = c0 + k;
            const float pv = __ldg(gp + k * CELLS);
            float tv, wgt;
            if (c <= 4) {                            // coords (chunk 0 only)
                tv  = tin ? __ldg(tb + c) : 0.0f;
                wgt = L_COORD;
            } else {                                 // class one-hot
                tv  = ((c - 5) == clsi) ? 1.0f : 0.0f;
                wgt = 1.0f;
            }
            const float d = pv - tv;
            sum += wgt * d * d;
        }
        if (!valid) sum = 0.0f;

        // ---- dedup'd conf0^2 subtraction (chunk 0 warps only; warp-uniform q) ----
        if (q == 0) {
            // within-half dedup: one match over lane keys
            const unsigned key = valid ? (unsigned)cell : (0x8000u + (unsigned)lane);
            const unsigned m = __match_any_sync(0xffffffffu, key);
            bool first = valid && ((m & ((1u << lane) - 1u)) == 0u);

            if (h == 1) {                            // also dedup vs targets 0..31
                const float* ob = tgt + ((size_t)b * T_TGT + lane) * 5;
                const float ox = __ldg(ob + 1);
                const float oy = __ldg(ob + 2);
                const int ogx = (int)(ox * S_GRID);
                const int ogy = (int)(oy * S_GRID);
                int oc = -1;
                if (ogx < S_GRID && ogy < S_GRID)
                    oc = min(max(ogy, 0), S_GRID - 1) * S_GRID
                       + min(max(ogx, 0), S_GRID - 1);
                #pragma unroll
                for (int j = 0; j < 32; j++) {
                    const int v = __shfl_sync(0xffffffffu, oc, j);
                    if (v == cell) first = false;
                }
            }
            if (first) {
                const float conf = __ldg(pb + cell); // channel 0
                sum = fmaf(-L_NOOBJ * conf, conf, sum);
            }
        }

        #pragma unroll
        for (int off = 16; off; off >>= 1)
            sum += __shfl_down_sync(0xffffffffu, sum, off);
        if (lane == 0) acc = sum;
    } else {
        // ---- conf^2 full sum: coalesced float4 sweep of channels 0,85,170 ----
        const int start  = (blockIdx.x - TGT_BLOCKS) * 256 + tid;
        const int stride = CONF_BLOCKS * 256;
        float csum = 0.0f;
        for (int i = start; i < BATCH_N * 3 * 169; i += stride) {
            const int b  = i / 507;                  // 3*169
            const int r  = i - b * 507;
            const int ch = r / 169;                  // channels 0, 85, 170
            const int j  = r - ch * 169;
            const float4 v = __ldg((const float4*)(pred
                              + (size_t)b * NCH * CELLS
                              + (size_t)(ch * 85) * CELLS) + j);
            csum += v.x * v.x + v.y * v.y + v.z * v.z + v.w * v.w;
        }
        acc = L_NOOBJ * csum;
        #pragma unroll
        for (int off = 16; off; off >>= 1)
            acc += __shfl_down_sync(0xffffffffu, acc, off);
        if (lane != 0) acc = 0.0f;
    }

    // ---- block reduce, then last-block-done finalization (single launch) ----
    if (lane == 0) s_warp[warp] = acc;
    __syncthreads();
    if (tid == 0) {
        float v = s_warp[0];
        #pragma unroll
        for (int w = 1; w < 8; w++) v += s_warp[w];
        if (v != 0.0f) atomicAdd(&g_acc, v);
        __threadfence();
        const unsigned ticket = atomicAdd(&g_cnt, 1u);
        if (ticket == NBLOCKS - 1) {
            const float total = atomicAdd(&g_acc, 0.0f);   // coherent read
            out[0] = total * (1.0f / BATCH_N);
            g_acc = 0.0f;                                  // replay-safe reset
            g_cnt = 0u;
        }
    }
}

extern "C" void kernel_launch(void* const* d_in, const int* in_sizes, int n_in,
                              void* d_out, int out_size)
{
    const float* pred = (const float*)d_in[0];
    const float* tgt  = (const float*)d_in[1];
    float* out = (float*)d_out;

    yolo_loss_kernel<<<NBLOCKS, 256>>>(pred, tgt, out);
}

// round 6
// speedup vs baseline: 1.2733x; 1.0500x over previous
#include <cuda_runtime.h>

// YOLO loss, sm_103a — round 5: transposed gather + 4-channel chunks for occupancy.
// warp = (image b, target-half h, channel-chunk q of 4). Lanes sweep cells inside
// one channel row (coalesced sectors), 5376 target warps hide DRAM latency.

#define S_GRID   26
#define NCH      255
#define CELLS    676
#define BATCH_N  128
#define T_TGT    50
#define L_COORD  5.0f
#define L_NOOBJ  0.5f

#define NCHUNK     21                        // 21 chunks * 4 channels = ch 1..84
#define TGT_WARPS  (BATCH_N * 2 * NCHUNK)    // 5376
#define TGT_BLOCKS (TGT_WARPS / 8)           // 672
#define CONF_BLOCKS 112
#define NBLOCKS    (TGT_BLOCKS + CONF_BLOCKS)

__device__ float    g_acc = 0.0f;            // reset by last block each call
__device__ unsigned g_cnt = 0u;

__global__ __launch_bounds__(256)
void yolo_loss_kernel(const float* __restrict__ pred,
                      const float* __restrict__ tgt,
                      float* __restrict__ out)
{
    const int tid  = threadIdx.x;
    const int lane = tid & 31;
    const int warp = tid >> 5;

    __shared__ float s_warp[8];

    float acc = 0.0f;

    if (blockIdx.x < TGT_BLOCKS) {
        // ---- target gather: warp = (image b, half h, chunk q) ----
        const int gw  = blockIdx.x * 8 + warp;       // 0..5375
        const int b   = gw / (2 * NCHUNK);
        const int rem = gw - b * (2 * NCHUNK);
        const int h   = rem / NCHUNK;                // 0 or 1
        const int q   = rem - h * NCHUNK;            // 0..20

        const int  t   = h * 32 + lane;              // this lane's target
        const bool tin = (t < T_TGT);
        const float* tb = tgt + ((size_t)b * T_TGT + t) * 5;

        float clsf = 0.0f, cx = 2.0f, cy = 2.0f;     // cx=2 -> invalid sentinel
        if (tin) {
            clsf = __ldg(tb + 0);
            cx   = __ldg(tb + 1);
            cy   = __ldg(tb + 2);
        }
        const int gx = (int)(cx * S_GRID);           // trunc == floor (cx >= 0)
        const int gy = (int)(cy * S_GRID);
        const bool valid = tin && (gx < S_GRID) && (gy < S_GRID);
        const int cell = min(max(gy, 0), S_GRID - 1) * S_GRID
                       + min(max(gx, 0), S_GRID - 1);
        const int clsi = (int)clsf;

        const float* pb = pred + (size_t)b * NCH * CELLS;
        const int c0 = 1 + q * 4;
        const float* gp = pb + (size_t)c0 * CELLS + cell;

        // 4 independent warp-coalesced gathers within channel rows
        float p[4];
        #pragma unroll
        for (int k = 0; k < 4; k++) p[k] = __ldg(gp + k * CELLS);

        float sum = 0.0f;
        if (q == 0) {
            // chunk 0 == the 4 coord channels (weight 5) + dedup duty
            #pragma unroll
            for (int k = 0; k < 4; k++) {
                const float tv = tin ? __ldg(tb + 1 + k) : 0.0f;
                const float d  = p[k] - tv;
                sum += d * d;
            }
            sum *= L_COORD;

            // ---- dedup'd conf0^2 subtraction ----
            const unsigned key = valid ? (unsigned)cell : (0x8000u + (unsigned)lane);
            const unsigned m = __match_any_sync(0xffffffffu, key);
            bool first = valid && ((m & ((1u << lane) - 1u)) == 0u);

            if (h == 1) {                            // dedup vs targets 0..31
                const float* ob = tgt + ((size_t)b * T_TGT + lane) * 5;
                const float ox = __ldg(ob + 1);
                const float oy = __ldg(ob + 2);
                const int ogx = (int)(ox * S_GRID);
                const int ogy = (int)(oy * S_GRID);
                int oc = -1;
                if (ogx < S_GRID && ogy < S_GRID)
                    oc = min(max(ogy, 0), S_GRID - 1) * S_GRID
                       + min(max(ogx, 0), S_GRID - 1);
                #pragma unroll
                for (int j = 0; j < 32; j++) {
                    const int v = __shfl_sync(0xffffffffu, oc, j);
                    if (v == cell) first = false;
                }
            }
            if (!valid) sum = 0.0f;
            if (first) {
                const float conf = __ldg(pb + cell); // channel 0
                sum = fmaf(-L_NOOBJ * conf, conf, sum);
            }
        } else {
            // class channels: one-hot target
            #pragma unroll
            for (int k = 0; k < 4; k++) {
                const float tv = ((c0 + k - 5) == clsi) ? 1.0f : 0.0f;
                const float d  = p[k] - tv;
                sum = fmaf(d, d, sum);
            }
            if (!valid) sum = 0.0f;
        }

        #pragma unroll
        for (int off = 16; off; off >>= 1)
            sum += __shfl_down_sync(0xffffffffu, sum, off);
        if (lane == 0) acc = sum;
    } else {
        // ---- conf^2 full sum: coalesced float4 sweep of channels 0,85,170 ----
        const int start  = (blockIdx.x - TGT_BLOCKS) * 256 + tid;
        const int stride = CONF_BLOCKS * 256;
        float csum = 0.0f;
        for (int i = start; i < BATCH_N * 3 * 169; i += stride) {
            const int b  = i / 507;                  // 3*169
            const int r  = i - b * 507;
            const int ch = r / 169;                  // channels 0, 85, 170
            const int j  = r - ch * 169;
            const float4 v = __ldg((const float4*)(pred
                              + (size_t)b * NCH * CELLS
                              + (size_t)(ch * 85) * CELLS) + j);
            csum += v.x * v.x + v.y * v.y + v.z * v.z + v.w * v.w;
        }
        acc = L_NOOBJ * csum;
        #pragma unroll
        for (int off = 16; off; off >>= 1)
            acc += __shfl_down_sync(0xffffffffu, acc, off);
        if (lane != 0) acc = 0.0f;
    }

    // ---- block reduce, then last-block-done finalization (single launch) ----
    if (lane == 0) s_warp[warp] = acc;
    __syncthreads();
    if (tid == 0) {
        float v = s_warp[0];
        #pragma unroll
        for (int w = 1; w < 8; w++) v += s_warp[w];
        if (v != 0.0f) atomicAdd(&g_acc, v);
        __threadfence();
        const unsigned ticket = atomicAdd(&g_cnt, 1u);
        if (ticket == NBLOCKS - 1) {
            const float total = atomicAdd(&g_acc, 0.0f);   // coherent read
            out[0] = total * (1.0f / BATCH_N);
            g_acc = 0.0f;                                  // replay-safe reset
            g_cnt = 0u;
        }
    }
}

extern "C" void kernel_launch(void* const* d_in, const int* in_sizes, int n_in,
                              void* d_out, int out_size)
{
    const float* pred = (const float*)d_in[0];
    const float* tgt  = (const float*)d_in[1];
    float* out = (float*)d_out;

    yolo_loss_kernel<<<NBLOCKS, 256>>>(pred, tgt, out);
}